// round 15
// baseline (speedup 1.0000x reference)
#include <cuda_runtime.h>
#include <cstdint>
#include <cstddef>

#define BB   16
#define PP   22536
#define NOBJ 32
#define NCLS 80
#define NROW (BB * PP)                       // 360,576
#define NE4  (NROW * (NCLS / 4))             // 7,211,520 float4 elements

#define OBJ_SPLITS 8
#define OBJ_CHUNK  (PP / OBJ_SPLITS)         // 2817 exactly
#define OBJ_TOT    (BB * NOBJ * OBJ_SPLITS)  // 4096 blocks

#define RS_ITER    5
#define RS_E4      (256 * RS_ITER)           // 1280 e4 per block = 64 rows exactly
#define RS_ROWS    64
#define RS_BLOCKS  (NE4 / RS_E4)             // 5634 exactly

#define FUSED_GX  ((PP + 255) / 256)         // 89
#define FUSED_BLOCKS (FUSED_GX * BB)         // 1424

#define MATCH_BASE  (OBJ_TOT + RS_BLOCKS)                 // 9730
#define MEGA_BLOCKS (OBJ_TOT + RS_BLOCKS + FUSED_BLOCKS)  // 11154

// ---------------- persistent device scratch (no allocs allowed) ---------------
__device__ unsigned long long g_obj_part[OBJ_TOT];   // partial keys, idx z*512 + b*32 + o
__device__ float g_confrow[NROW];            // unweighted per-row focal sum (g/ln2)
__device__ int   g_match[NROW];              // packed (besto<<8)|(t_unforced+1)
__device__ float g_conf_part[2048];          // per-fused-block conf (incl. corrections)
__device__ float g_loc_part[2048];
__device__ int   g_npos_part[2048];
__device__ unsigned g_done;

// ---------------- MUFU wrappers ------------------------------------------------
__device__ __forceinline__ float tanhf_a(float x) {
    float r;
    asm("tanh.approx.f32 %0, %1;" : "=f"(r) : "f"(x));
    return r;
}
__device__ __forceinline__ float lg2f(float x) {
    float r;
    asm("lg2.approx.f32 %0, %1;" : "=f"(r) : "f"(x));
    return r;
}

// 2-MUFU focal core: returns g(x)/ln2 where g(x) = sigmoid(x)^2 * softplus(x)
__device__ __forceinline__ float gfun_t(float x) {
    float T = tanhf_a(0.5f * x);
    float s = fmaf(0.5f, T, 0.5f);
    float u = fmaf(-0.5f, T, 0.5f);
    float L = lg2f(u);
    return -(s * s) * L;
}

__device__ __forceinline__ float sl1(float d) {
    float ad = fabsf(d);
    return (ad < 1.0f) ? 0.5f * d * d : ad - 0.5f;
}

// -------- IoU with precomputed box area (bitwise identical arithmetic) --------
__device__ __forceinline__ float iou_ab(float px1, float py1, float px2, float py2,
                                        float parea, float4 bx, float ab) {
    float ltx = fmaxf(px1, bx.x), lty = fmaxf(py1, bx.y);
    float rbx = fminf(px2, bx.z), rby = fminf(py2, bx.w);
    float iw = fmaxf(rbx - ltx, 0.0f), ih = fmaxf(rby - lty, 0.0f);
    float inter = iw * ih;
    return __fdividef(inter, parea + ab - inter);
}

// ======== MEGA: three independent block families ==============================
__global__ void __launch_bounds__(256)
k_mega(const float* __restrict__ pscores,
       const float* __restrict__ boxes, const float* __restrict__ priors,
       const int* __restrict__ labels) {
    __shared__ float s_part[RS_E4];                 // rowsum staging (5 KB)
    __shared__ unsigned long long swk[8];
    __shared__ float4 sbox[NOBJ];
    __shared__ float  sarea[NOBJ];

    // deterministic counter reset for k_fused's amLast reduction
    if (blockIdx.x == 0 && threadIdx.x == 0) g_done = 0u;

    if (blockIdx.x < OBJ_TOT) {
        // -------- family A: per-object partial argmax over a prior chunk ------
        int idx = blockIdx.x;
        int o = idx & (NOBJ - 1);
        int b = (idx >> 5) & (BB - 1);
        int z = idx >> 9;
        float4 bx = ((const float4*)boxes)[b * NOBJ + o];
        float ab = (bx.z - bx.x) * (bx.w - bx.y);   // loop-invariant

        int pr0 = z * OBJ_CHUNK;
        int pr1 = pr0 + OBJ_CHUNK;

        float best = 0.0f;          // only iou>0 can matter (key 0 = invalid)
        int   bestpr = -1;
        for (int pr = pr0 + threadIdx.x; pr < pr1; pr += 256) {
            float4 pc = ((const float4*)priors)[pr];
            float hx = 0.5f * pc.z, hy = 0.5f * pc.w;
            float px1 = pc.x - hx, py1 = pc.y - hy;
            float px2 = pc.x + hx, py2 = pc.y + hy;
            float parea = (px2 - px1) * (py2 - py1);
            float iou = iou_ab(px1, py1, px2, py2, parea, bx, ab);
            if (iou > best) { best = iou; bestpr = pr; }   // strict > : smallest pr
        }
        unsigned long long key = 0ull;
        if (bestpr >= 0)
            key = (((unsigned long long)__float_as_uint(best)) << 32)
                | (unsigned long long)(0xFFFFFFFFu - (unsigned)bestpr);

        #pragma unroll
        for (int s = 16; s > 0; s >>= 1) {
            unsigned long long other = __shfl_xor_sync(0xFFFFFFFFu, key, s);
            if (other > key) key = other;
        }
        int lane = threadIdx.x & 31, wid = threadIdx.x >> 5;
        if (lane == 0) swk[wid] = key;
        __syncthreads();
        if (threadIdx.x == 0) {
            #pragma unroll
            for (int w = 1; w < 8; w++)
                if (swk[w] > key) key = swk[w];
            g_obj_part[idx] = key;
        }
    } else if (blockIdx.x < MATCH_BASE) {
        // -------- family B: unweighted per-row focal sums (coalesced) ---------
        int rb = blockIdx.x - OBJ_TOT;
        const float4* sc4 = (const float4*)pscores;
        int base = rb * RS_E4;

        #pragma unroll
        for (int it = 0; it < RS_ITER; it++) {
            int l4 = it * 256 + threadIdx.x;
            float4 v = sc4[base + l4];
            float s4 = gfun_t(v.x) + gfun_t(v.y) + gfun_t(v.z) + gfun_t(v.w);
            s_part[l4] = s4;
        }
        __syncthreads();
        if (threadIdx.x < RS_ROWS) {
            const float* p = &s_part[threadIdx.x * (NCLS / 4)];
            float s = 0.0f;
            #pragma unroll
            for (int k = 0; k < NCLS / 4; k++) s += p[k];
            g_confrow[rb * RS_ROWS + threadIdx.x] = s;
        }
    } else {
        // -------- family C: per-prior unforced argmax + target ---------------
        int cidx = blockIdx.x - MATCH_BASE;
        int b  = cidx / FUSED_GX;
        int gx = cidx - b * FUSED_GX;
        int pr = gx * 256 + threadIdx.x;

        if (threadIdx.x < NOBJ) {
            float4 bxs = ((const float4*)boxes)[b * NOBJ + threadIdx.x];
            sbox[threadIdx.x]  = bxs;
            sarea[threadIdx.x] = (bxs.z - bxs.x) * (bxs.w - bxs.y);
        }
        __syncthreads();

        if (pr < PP) {
            float4 pc = ((const float4*)priors)[pr];
            float hx = 0.5f * pc.z, hy = 0.5f * pc.w;
            float px1 = pc.x - hx, py1 = pc.y - hy;
            float px2 = pc.x + hx, py2 = pc.y + hy;
            float parea = (px2 - px1) * (py2 - py1);

            float best = -1.0f;
            int   besto = 0;
            #pragma unroll 8
            for (int o = 0; o < NOBJ; o++) {
                float iou = iou_ab(px1, py1, px2, py2, parea, sbox[o], sarea[o]);
                if (iou > best) { best = iou; besto = o; }   // strict > => first-max
            }
            int t = 0;
            if (best >= 0.4f)
                t = (best < 0.5f) ? -1 : labels[b * NOBJ + besto];
            g_match[b * PP + pr] = (besto << 8) | (t + 1);   // t+1 in [0,81]
        }
    }
}

// ======== FUSED: override + weighted conf + sparse extras + final =============
__global__ void __launch_bounds__(256)
k_fused(const float* __restrict__ plocs, const float* __restrict__ pscores,
        const float* __restrict__ boxes, const int* __restrict__ labels,
        const float* __restrict__ priors, float* __restrict__ out) {
    const float LN2 = 0.6931471805599453f;
    const float SCALEF = 0.75f * 0.6931471805599453f;   // 0.75*ln2
    int b    = blockIdx.y;
    int blk0 = blockIdx.x * 256;
    int pr   = blk0 + threadIdx.x;

    __shared__ float4 sbox[NOBJ];
    __shared__ int sprior[NOBJ];
    __shared__ int scnt[NOBJ];
    __shared__ int s_has;
    if (threadIdx.x < NOBJ) {
        sbox[threadIdx.x] = ((const float4*)boxes)[b * NOBJ + threadIdx.x];
        // reduce over splits: layout is idx = z*(BB*NOBJ) + b*NOBJ + o
        unsigned long long key = 0ull;
        #pragma unroll
        for (int z = 0; z < OBJ_SPLITS; z++) {
            unsigned long long k2 = g_obj_part[z * (BB * NOBJ) + b * NOBJ + threadIdx.x];
            if (k2 > key) key = k2;
        }
        float ovj = __uint_as_float((unsigned)(key >> 32));
        int valid = (ovj > 0.0f) ? 1 : 0;
        unsigned m = __ballot_sync(0xFFFFFFFFu, valid);
        int prj = valid ? (int)(0xFFFFFFFFu - (unsigned)(key & 0xFFFFFFFFull)) : -1;
        sprior[threadIdx.x] = prj;
        scnt[threadIdx.x]   = __popc(m & ((1u << threadIdx.x) - 1u));
        // does any forced prior land in this block's range?
        unsigned inr = __ballot_sync(0xFFFFFFFFu, prj >= blk0 && prj < blk0 + 256);
        if (threadIdx.x == 0) s_has = (inr != 0u);
    }
    __syncthreads();

    float conf = 0.0f, loc = 0.0f;
    int np = 0;

    if (pr < PP) {
        int row = b * PP + pr;
        int m   = g_match[row];
        int obj = m >> 8;
        int t   = (m & 0xFF) - 1;

        // forced override: ascending j, later valid objects overwrite (jax scatter)
        if (s_has) {
            #pragma unroll
            for (int j = 0; j < NOBJ; j++) {
                if (sprior[j] == pr) { obj = scnt[j]; t = labels[b * NOBJ + obj]; }
            }
        }

        if (t >= 0)
            conf = SCALEF * g_confrow[row];

        if (t > 0) {
            np = 1;
            float xk = pscores[(size_t)row * NCLS + (t - 1)];
            conf += LN2 * (0.25f * gfun_t(-xk) - 0.75f * gfun_t(xk));

            float4 pc = ((const float4*)priors)[pr];
            float4 bx = sbox[obj];
            float cx = 0.5f * (bx.x + bx.z), cy = 0.5f * (bx.y + bx.w);
            float w2 = bx.z - bx.x,          h2 = bx.w - bx.y;
            float g0 = __fdividef(cx - pc.x, 0.1f * pc.z);
            float g1 = __fdividef(cy - pc.y, 0.1f * pc.w);
            float g2 = 5.0f * __logf(__fdividef(w2, pc.z));
            float g3 = 5.0f * __logf(__fdividef(h2, pc.w));
            float4 pl = ((const float4*)plocs)[row];
            loc = sl1(pl.x - g0) + sl1(pl.y - g1) + sl1(pl.z - g2) + sl1(pl.w - g3);
        }
    }

    #pragma unroll
    for (int s = 16; s > 0; s >>= 1) {
        conf += __shfl_xor_sync(0xFFFFFFFFu, conf, s);
        loc  += __shfl_xor_sync(0xFFFFFFFFu, loc, s);
        np   += __shfl_xor_sync(0xFFFFFFFFu, np, s);
    }
    __shared__ float swc[8], swl[8];
    __shared__ int   swn[8];
    int lane = threadIdx.x & 31, wid = threadIdx.x >> 5;
    if (lane == 0) { swc[wid] = conf; swl[wid] = loc; swn[wid] = np; }
    __syncthreads();

    __shared__ bool amLast;
    int cidx = blockIdx.y * gridDim.x + blockIdx.x;
    if (threadIdx.x == 0) {
        float c = 0.0f, l = 0.0f; int n = 0;
        #pragma unroll
        for (int w = 0; w < 8; w++) { c += swc[w]; l += swl[w]; n += swn[w]; }
        g_conf_part[cidx] = c;
        g_loc_part[cidx]  = l;
        g_npos_part[cidx] = n;
        __threadfence();
        unsigned v = atomicAdd(&g_done, 1u);
        amLast = (v == (unsigned)(FUSED_BLOCKS - 1));
    }
    __syncthreads();

    if (amLast) {
        __shared__ double sc[256];
        __shared__ double sl[256];
        __shared__ int    sn[256];
        int tid = threadIdx.x;
        double c = 0.0, l = 0.0;
        int n = 0;
        for (int i = tid; i < FUSED_BLOCKS; i += 256) {
            c += (double)g_conf_part[i];
            l += (double)g_loc_part[i];
            n += g_npos_part[i];
        }
        sc[tid] = c; sl[tid] = l; sn[tid] = n;
        __syncthreads();
        #pragma unroll
        for (int s = 128; s > 0; s >>= 1) {
            if (tid < s) {
                sc[tid] += sc[tid + s];
                sl[tid] += sl[tid + s];
                sn[tid] += sn[tid + s];
            }
            __syncthreads();
        }
        if (tid == 0) {
            double npos = (double)(sn[0] > 1 ? sn[0] : 1);
            out[0] = (float)(sc[0] / npos + sl[0] / (npos * 4.0));
        }
    }
}

// ---------------- launch ---------------------------------------------------------
extern "C" void kernel_launch(void* const* d_in, const int* in_sizes, int n_in,
                              void* d_out, int out_size) {
    const float* plocs   = (const float*)d_in[0];
    const float* pscores = (const float*)d_in[1];
    const float* boxes   = (const float*)d_in[2];
    const int*   labels  = (const int*)d_in[3];
    const float* priors  = (const float*)d_in[4];
    float* out = (float*)d_out;

    k_mega<<<MEGA_BLOCKS, 256>>>(pscores, boxes, priors, labels);

    dim3 fg(FUSED_GX, BB);
    k_fused<<<fg, 256>>>(plocs, pscores, boxes, labels, priors, out);
}

// round 16
// speedup vs baseline: 1.1687x; 1.1687x over previous
#include <cuda_runtime.h>
#include <cstdint>
#include <cstddef>

#define BB   16
#define PP   22536
#define NOBJ 32
#define NCLS 80
#define NROW (BB * PP)                       // 360,576
#define NE4  (NROW * (NCLS / 4))             // 7,211,520 float4 elements
#define NPAIR (BB * NOBJ)                    // 512

#define RS_ITER    5
#define RS_E4      (256 * RS_ITER)           // 1280 e4 per block = 64 rows exactly
#define RS_ROWS    64
#define RS_BLOCKS  (NE4 / RS_E4)             // 5634 exactly

#define M_GX       ((PP + 255) / 256)        // 89 chunks per image
#define M_BLOCKS   (M_GX * BB)               // 1424 merged blocks
#define MEGA_BLOCKS (M_BLOCKS + RS_BLOCKS)   // 7058

#define FUSED_GX  M_GX                       // 89
#define FUSED_BLOCKS (FUSED_GX * BB)         // 1424

// ---------------- persistent device scratch (no allocs allowed) ---------------
__device__ unsigned long long g_obj_key[NPAIR];   // per-(b,o) best (iou,~pr) key; zeroed at end of k_fused
__device__ float g_confrow[NROW];            // unweighted per-row focal sum (g/ln2)
__device__ int   g_match[NROW];              // packed (besto<<8)|(t_unforced+1)
__device__ float g_conf_part[2048];
__device__ float g_loc_part[2048];
__device__ int   g_npos_part[2048];
__device__ unsigned g_done;

// ---------------- MUFU wrappers ------------------------------------------------
__device__ __forceinline__ float tanhf_a(float x) {
    float r;
    asm("tanh.approx.f32 %0, %1;" : "=f"(r) : "f"(x));
    return r;
}
__device__ __forceinline__ float lg2f(float x) {
    float r;
    asm("lg2.approx.f32 %0, %1;" : "=f"(r) : "f"(x));
    return r;
}

// 2-MUFU focal core: returns g(x)/ln2 where g(x) = sigmoid(x)^2 * softplus(x)
__device__ __forceinline__ float gfun_t(float x) {
    float T = tanhf_a(0.5f * x);
    float s = fmaf(0.5f, T, 0.5f);
    float u = fmaf(-0.5f, T, 0.5f);
    float L = lg2f(u);
    return -(s * s) * L;
}

__device__ __forceinline__ float sl1(float d) {
    float ad = fabsf(d);
    return (ad < 1.0f) ? 0.5f * d * d : ad - 0.5f;
}

// -------- IoU with precomputed box area (bitwise identical arithmetic) --------
__device__ __forceinline__ float iou_ab(float px1, float py1, float px2, float py2,
                                        float parea, float4 bx, float ab) {
    float ltx = fmaxf(px1, bx.x), lty = fmaxf(py1, bx.y);
    float rbx = fminf(px2, bx.z), rby = fminf(py2, bx.w);
    float iw = fmaxf(rbx - ltx, 0.0f), ih = fmaxf(rby - lty, 0.0f);
    float inter = iw * ih;
    return __fdividef(inter, parea + ab - inter);
}

// ======== MEGA: merged-matching blocks + rowsum blocks ========================
__global__ void __launch_bounds__(256)
k_mega(const float* __restrict__ pscores,
       const float* __restrict__ boxes, const float* __restrict__ priors,
       const int* __restrict__ labels) {
    // union pool: merged needs 16*257 floats (16.4KB); rowsum needs 1280 floats
    __shared__ float s_pool[16 * 257];
    __shared__ float4 sbox[NOBJ];
    __shared__ float  sarea[NOBJ];

    // deterministic counter reset for k_fused's amLast reduction
    if (blockIdx.x == 0 && threadIdx.x == 0) g_done = 0u;

    if (blockIdx.x < M_BLOCKS) {
        // ======= merged family: one IoU pass -> both reductions ===============
        int cidx = blockIdx.x;
        int b  = cidx / M_GX;
        int gx = cidx - b * M_GX;
        int base = gx * 256;
        int pr   = base + threadIdx.x;
        bool live = (pr < PP);

        if (threadIdx.x < NOBJ) {
            float4 bxs = ((const float4*)boxes)[b * NOBJ + threadIdx.x];
            sbox[threadIdx.x]  = bxs;
            sarea[threadIdx.x] = (bxs.z - bxs.x) * (bxs.w - bxs.y);
        }
        __syncthreads();

        float px1, py1, px2, py2, parea;
        if (live) {
            float4 pc = ((const float4*)priors)[pr];
            float hx = 0.5f * pc.z, hy = 0.5f * pc.w;
            px1 = pc.x - hx; py1 = pc.y - hy;
            px2 = pc.x + hx; py2 = pc.y + hy;
            parea = (px2 - px1) * (py2 - py1);
        } else {
            // degenerate far-away box -> iou = 0 for every object
            px1 = py1 = px2 = py2 = 1.0e30f;
            parea = 0.0f;
        }

        // per-prior argmax: 4 contiguous ILP chains of 8 objects each
        float bests[4] = {-1.0f, -1.0f, -1.0f, -1.0f};
        int   bestos[4] = {0, 8, 16, 24};

        int oj = threadIdx.x >> 4;     // phase-2: local object 0..15
        int k  = threadIdx.x & 15;     // phase-2: slice index

        #pragma unroll
        for (int half = 0; half < 2; half++) {
            int base_o = half * 16;
            #pragma unroll
            for (int j = 0; j < 16; j++) {
                int o = base_o + j;
                float iou = iou_ab(px1, py1, px2, py2, parea, sbox[o], sarea[o]);
                s_pool[j * 257 + threadIdx.x] = iou;
                int c = o >> 3;
                if (iou > bests[c]) { bests[c] = iou; bestos[c] = o; }
            }
            __syncthreads();

            // per-object max over this block's 256 priors (16 threads/object)
            unsigned long long key = 0ull;
            #pragma unroll
            for (int i = 0; i < 16; i++) {
                int prl = k + (i << 4);            // strided, order-independent
                float v = s_pool[oj * 257 + prl];
                if (v > 0.0f) {
                    unsigned long long kk =
                        (((unsigned long long)__float_as_uint(v)) << 32)
                        | (unsigned long long)(0xFFFFFFFFu - (unsigned)(base + prl));
                    if (kk > key) key = kk;
                }
            }
            #pragma unroll
            for (int s = 8; s > 0; s >>= 1) {
                unsigned long long o2 = __shfl_xor_sync(0xFFFFFFFFu, key, s);
                if (o2 > key) key = o2;
            }
            if (k == 0 && key != 0ull)
                atomicMax(&g_obj_key[b * NOBJ + base_o + oj], key);
            __syncthreads();   // before smem reuse in next half
        }

        if (live) {
            // combine chains in ascending-o order => first-max semantics
            float best = bests[0]; int besto = bestos[0];
            #pragma unroll
            for (int c = 1; c < 4; c++)
                if (bests[c] > best) { best = bests[c]; besto = bestos[c]; }
            int t = 0;
            if (best >= 0.4f)
                t = (best < 0.5f) ? -1 : labels[b * NOBJ + besto];
            g_match[b * PP + pr] = (besto << 8) | (t + 1);   // t+1 in [0,81]
        }
    } else {
        // ======= rowsum family: unweighted per-row focal sums =================
        int rb = blockIdx.x - M_BLOCKS;
        const float4* sc4 = (const float4*)pscores;
        int base = rb * RS_E4;

        #pragma unroll
        for (int it = 0; it < RS_ITER; it++) {
            int l4 = it * 256 + threadIdx.x;
            float4 v = sc4[base + l4];
            float s4 = gfun_t(v.x) + gfun_t(v.y) + gfun_t(v.z) + gfun_t(v.w);
            s_pool[l4] = s4;
        }
        __syncthreads();
        if (threadIdx.x < RS_ROWS) {
            const float* p = &s_pool[threadIdx.x * (NCLS / 4)];
            float s = 0.0f;
            #pragma unroll
            for (int kk = 0; kk < NCLS / 4; kk++) s += p[kk];
            g_confrow[rb * RS_ROWS + threadIdx.x] = s;
        }
    }
}

// ======== FUSED: override + weighted conf + sparse extras + final =============
__global__ void __launch_bounds__(256)
k_fused(const float* __restrict__ plocs, const float* __restrict__ pscores,
        const float* __restrict__ boxes, const int* __restrict__ labels,
        const float* __restrict__ priors, float* __restrict__ out) {
    const float LN2 = 0.6931471805599453f;
    const float SCALEF = 0.75f * 0.6931471805599453f;   // 0.75*ln2
    int b    = blockIdx.y;
    int blk0 = blockIdx.x * 256;
    int pr   = blk0 + threadIdx.x;

    __shared__ float4 sbox[NOBJ];
    __shared__ int sprior[NOBJ];
    __shared__ int scnt[NOBJ];
    __shared__ int s_has;
    if (threadIdx.x < NOBJ) {
        sbox[threadIdx.x] = ((const float4*)boxes)[b * NOBJ + threadIdx.x];
        unsigned long long key = g_obj_key[b * NOBJ + threadIdx.x];
        float ovj = __uint_as_float((unsigned)(key >> 32));
        int valid = (ovj > 0.0f) ? 1 : 0;
        unsigned m = __ballot_sync(0xFFFFFFFFu, valid);
        int prj = valid ? (int)(0xFFFFFFFFu - (unsigned)(key & 0xFFFFFFFFull)) : -1;
        sprior[threadIdx.x] = prj;
        scnt[threadIdx.x]   = __popc(m & ((1u << threadIdx.x) - 1u));
        unsigned inr = __ballot_sync(0xFFFFFFFFu, prj >= blk0 && prj < blk0 + 256);
        if (threadIdx.x == 0) s_has = (inr != 0u);
    }
    __syncthreads();

    float conf = 0.0f, loc = 0.0f;
    int np = 0;

    if (pr < PP) {
        int row = b * PP + pr;
        int m   = g_match[row];
        int obj = m >> 8;
        int t   = (m & 0xFF) - 1;

        // forced override: ascending j, later valid objects overwrite (jax scatter)
        if (s_has) {
            #pragma unroll
            for (int j = 0; j < NOBJ; j++) {
                if (sprior[j] == pr) { obj = scnt[j]; t = labels[b * NOBJ + obj]; }
            }
        }

        if (t >= 0)
            conf = SCALEF * g_confrow[row];

        if (t > 0) {
            np = 1;
            float xk = pscores[(size_t)row * NCLS + (t - 1)];
            conf += LN2 * (0.25f * gfun_t(-xk) - 0.75f * gfun_t(xk));

            float4 pc = ((const float4*)priors)[pr];
            float4 bx = sbox[obj];
            float cx = 0.5f * (bx.x + bx.z), cy = 0.5f * (bx.y + bx.w);
            float w2 = bx.z - bx.x,          h2 = bx.w - bx.y;
            float g0 = __fdividef(cx - pc.x, 0.1f * pc.z);
            float g1 = __fdividef(cy - pc.y, 0.1f * pc.w);
            float g2 = 5.0f * __logf(__fdividef(w2, pc.z));
            float g3 = 5.0f * __logf(__fdividef(h2, pc.w));
            float4 pl = ((const float4*)plocs)[row];
            loc = sl1(pl.x - g0) + sl1(pl.y - g1) + sl1(pl.z - g2) + sl1(pl.w - g3);
        }
    }

    #pragma unroll
    for (int s = 16; s > 0; s >>= 1) {
        conf += __shfl_xor_sync(0xFFFFFFFFu, conf, s);
        loc  += __shfl_xor_sync(0xFFFFFFFFu, loc, s);
        np   += __shfl_xor_sync(0xFFFFFFFFu, np, s);
    }
    __shared__ float swc[8], swl[8];
    __shared__ int   swn[8];
    int lane = threadIdx.x & 31, wid = threadIdx.x >> 5;
    if (lane == 0) { swc[wid] = conf; swl[wid] = loc; swn[wid] = np; }
    __syncthreads();

    __shared__ bool amLast;
    int cidx = blockIdx.y * gridDim.x + blockIdx.x;
    if (threadIdx.x == 0) {
        float c = 0.0f, l = 0.0f; int n = 0;
        #pragma unroll
        for (int w = 0; w < 8; w++) { c += swc[w]; l += swl[w]; n += swn[w]; }
        g_conf_part[cidx] = c;
        g_loc_part[cidx]  = l;
        g_npos_part[cidx] = n;
        __threadfence();
        unsigned v = atomicAdd(&g_done, 1u);
        amLast = (v == (unsigned)(FUSED_BLOCKS - 1));
    }
    __syncthreads();

    if (amLast) {
        __shared__ double sc[256];
        __shared__ double sl[256];
        __shared__ int    sn[256];
        int tid = threadIdx.x;
        double c = 0.0, l = 0.0;
        int n = 0;
        for (int i = tid; i < FUSED_BLOCKS; i += 256) {
            c += (double)g_conf_part[i];
            l += (double)g_loc_part[i];
            n += g_npos_part[i];
        }
        sc[tid] = c; sl[tid] = l; sn[tid] = n;
        __syncthreads();
        #pragma unroll
        for (int s = 128; s > 0; s >>= 1) {
            if (tid < s) {
                sc[tid] += sc[tid + s];
                sl[tid] += sl[tid + s];
                sn[tid] += sn[tid + s];
            }
            __syncthreads();
        }
        if (tid == 0) {
            double npos = (double)(sn[0] > 1 ? sn[0] : 1);
            out[0] = (float)(sc[0] / npos + sl[0] / (npos * 4.0));
        }
        // zero g_obj_key for next run/replay (all readers have already arrived)
        for (int i = tid; i < NPAIR; i += 256)
            g_obj_key[i] = 0ull;
    }
}

// ---------------- launch ---------------------------------------------------------
extern "C" void kernel_launch(void* const* d_in, const int* in_sizes, int n_in,
                              void* d_out, int out_size) {
    const float* plocs   = (const float*)d_in[0];
    const float* pscores = (const float*)d_in[1];
    const float* boxes   = (const float*)d_in[2];
    const int*   labels  = (const int*)d_in[3];
    const float* priors  = (const float*)d_in[4];
    float* out = (float*)d_out;

    k_mega<<<MEGA_BLOCKS, 256>>>(pscores, boxes, priors, labels);

    dim3 fg(FUSED_GX, BB);
    k_fused<<<fg, 256>>>(plocs, pscores, boxes, labels, priors, out);
}